// round 2
// baseline (speedup 1.0000x reference)
#include <cuda_runtime.h>
#include <cstdint>

#define B_ 8
#define H_ 1024
#define W_ 1024
#define HW_ (H_*W_)
#define K_ 2048
#define CAP_ 262144
#define SURV_ 4096
#define NBIN_ 2048
#define NCELL_ 1024   /* 32x32 grid */
#define CELL_INV (1.0f/256.0f)
#define EMAX_ 512

// ---------------- scratch (static device memory only; no allocs) ----------------
__device__ unsigned long long g_cand[B_][CAP_];
__device__ int g_cnt[B_];
__device__ unsigned long long g_topk[B_][K_];

// ---------------- K0: reset counters ----------------
__global__ void k_reset() {
    if (threadIdx.x < B_) g_cnt[threadIdx.x] = 0;
}

// ---------------- K1: local-max candidates ----------------
// block = one image row (256 threads x 4 pixels), grid = (H, B)
__global__ void __launch_bounds__(256) k_cand(const float* __restrict__ sc) {
    const int b = blockIdx.y, h = blockIdx.x;
    const int w0 = threadIdx.x * 4;
    const float* rc = sc + ((size_t)b * H_ + h) * W_;
    const float NI = -__int_as_float(0x7f800000); // -inf

    float4 c4 = *reinterpret_cast<const float4*>(rc + w0);
    float cL = (w0 > 0)        ? rc[w0-1] : NI;
    float cR = (w0 + 4 < W_)   ? rc[w0+4] : NI;
    float4 u4 = make_float4(NI,NI,NI,NI), d4 = make_float4(NI,NI,NI,NI);
    float uL=NI,uR=NI,dL=NI,dR=NI;
    if (h > 0) {
        const float* ru = rc - W_;
        u4 = *reinterpret_cast<const float4*>(ru + w0);
        uL = (w0 > 0)      ? ru[w0-1] : NI;
        uR = (w0 + 4 < W_) ? ru[w0+4] : NI;
    }
    if (h < H_-1) {
        const float* rd = rc + W_;
        d4 = *reinterpret_cast<const float4*>(rd + w0);
        dL = (w0 > 0)      ? rd[w0-1] : NI;
        dR = (w0 + 4 < W_) ? rd[w0+4] : NI;
    }
    float cv[6] = {cL, c4.x, c4.y, c4.z, c4.w, cR};
    float uv[6] = {uL, u4.x, u4.y, u4.z, u4.w, uR};
    float dv[6] = {dL, d4.x, d4.y, d4.z, d4.w, dR};

    #pragma unroll
    for (int p = 0; p < 4; p++) {
        float s = cv[p+1];
        float nb = fmaxf(fmaxf(cv[p], cv[p+2]),
                   fmaxf(fmaxf(fmaxf(uv[p], uv[p+1]), uv[p+2]),
                         fmaxf(fmaxf(dv[p], dv[p+1]), dv[p+2])));
        bool cand = (s > 0.5f) && (s >= nb);   // s == 3x3 maxpool  <=>  s >= all 8 neighbors
        unsigned mask = __ballot_sync(0xffffffffu, cand);
        if (cand) {
            int lane = threadIdx.x & 31;
            int leader = __ffs(mask) - 1;
            int base = 0;
            if (lane == leader) base = atomicAdd(&g_cnt[b], __popc(mask));
            base = __shfl_sync(mask, base, leader);
            int pos = base + __popc(mask & ((1u << lane) - 1u));
            if (pos < CAP_) {
                unsigned idx = (unsigned)(h * W_ + w0 + p);
                unsigned sb = __float_as_uint(s);   // s > 0.5 -> positive, bits order == value order
                // key: higher score first; tie -> smaller idx first (matches lax.top_k)
                g_cand[b][pos] = ((unsigned long long)sb << 32) | (unsigned)(~idx);
            }
        }
    }
}

// ---------------- K2: per-batch exact sorted top-K ----------------
__global__ void __launch_bounds__(1024) k_topk() {
    const int b = blockIdx.x, tid = threadIdx.x;
    __shared__ unsigned hist[NBIN_];               // 8 KB (histogram -> suffix sums)
    __shared__ unsigned long long buf[SURV_];      // 32 KB survivors
    __shared__ int sT, sW;

    int n = g_cnt[b]; if (n > CAP_) n = CAP_;
    hist[tid] = 0; hist[tid + 1024] = 0;
    if (tid == 0) { sT = 0; sW = 0; }
    __syncthreads();

    // histogram on top-11 mantissa bits (all scores in (0.5,1) -> fixed exponent 126)
    for (int i = tid; i < n; i += 1024) {
        unsigned bits = (unsigned)(g_cand[b][i] >> 32);
        atomicAdd(&hist[(bits >> 12) & (NBIN_-1)], 1u);
    }
    __syncthreads();

    // inclusive suffix sums: hist[i] = #candidates with bin >= i
    for (int off = 1; off < NBIN_; off <<= 1) {
        unsigned v0 = hist[tid]      + ((tid + off        < NBIN_) ? hist[tid + off]        : 0u);
        unsigned v1 = hist[tid+1024] + ((tid + 1024 + off < NBIN_) ? hist[tid + 1024 + off] : 0u);
        __syncthreads();
        hist[tid] = v0; hist[tid + 1024] = v1;
        __syncthreads();
    }

    // threshold bin T: largest bin with suffix >= K
    for (int i = tid; i < NBIN_; i += 1024) {
        unsigned sfx = hist[i];
        unsigned nxt = (i + 1 < NBIN_) ? hist[i+1] : 0u;
        if (sfx >= K_ && nxt < K_) sT = i;
    }
    __syncthreads();
    int T = sT;

    // compact survivors (bin >= T) into shared
    for (int i = tid; i < n; i += 1024) {
        unsigned long long key = g_cand[b][i];
        unsigned bits = (unsigned)(key >> 32);
        if ((int)((bits >> 12) & (NBIN_-1)) >= T) {
            int p = atomicAdd(&sW, 1);
            if (p < SURV_) buf[p] = key;
        }
    }
    __syncthreads();
    int M = sW; if (M > SURV_) M = SURV_;
    for (int i = tid; i < SURV_; i += 1024) if (i >= M) buf[i] = 0ull;
    __syncthreads();

    // bitonic sort, descending (keys unique: idx differs)
    for (int kk = 2; kk <= SURV_; kk <<= 1) {
        for (int j = kk >> 1; j > 0; j >>= 1) {
            for (int i = tid; i < SURV_; i += 1024) {
                int l = i ^ j;
                if (l > i) {
                    unsigned long long a = buf[i], c = buf[l];
                    bool up = ((i & kk) == 0);
                    if (up ? (a < c) : (a > c)) { buf[i] = c; buf[l] = a; }
                }
            }
            __syncthreads();
        }
    }
    for (int i = tid; i < K_; i += 1024) g_topk[b][i] = buf[i];
}

// ---------------- K3: box decode + sparse-edge greedy NMS + outputs ----------------
__global__ void __launch_bounds__(1024) k_nms(
    const float* __restrict__ deltas, const float* __restrict__ sizes,
    const int* __restrict__ p_stride, const int* __restrict__ p_offy,
    const int* __restrict__ p_offx,
    float* __restrict__ out, int out_size)
{
    const int b = blockIdx.x, tid = threadIdx.x;
    __shared__ float bx1[K_], by1[K_], bx2[K_], by2[K_];   // 32 KB
    __shared__ unsigned cellcnt[NCELL_];                   // 4 KB (counts -> cursors)
    __shared__ unsigned short cstart[NCELL_ + 2];          // cell segment starts
    __shared__ unsigned short list[K_];                    // boxes sorted by cell
    __shared__ unsigned char keepA[K_];
    __shared__ unsigned edges[EMAX_];
    __shared__ unsigned wsum[32];
    __shared__ int sE;

    const int stride = *p_stride, offy = *p_offy, offx = *p_offx;
    if (tid == 0) sE = 0;
    cellcnt[tid] = 0;
    __syncthreads();

    // decode boxes (exact f32 op order as reference)
    for (int t = tid; t < K_; t += 1024) {
        unsigned long long key = g_topk[b][t];
        bool valid = key != 0ull;
        unsigned idx = ~(unsigned)key;
        float x1=0.f, y1=0.f, x2=0.f, y2=0.f;
        if (valid) {
            int iw = (int)(idx & (W_-1)), ih = (int)(idx >> 10);
            float dx = deltas[((size_t)b*2 + 0)*HW_ + idx];
            float dy = deltas[((size_t)b*2 + 1)*HW_ + idx];
            float sx = sizes [((size_t)b*2 + 0)*HW_ + idx];
            float sy = sizes [((size_t)b*2 + 1)*HW_ + idx];
            float cx = (float)(iw*stride + offx) + dx;
            float cy = (float)(ih*stride + offy) + dy;
            x1 = cx - sx*0.5f; x2 = cx + sx*0.5f;
            y1 = cy - sy*0.5f; y2 = cy + sy*0.5f;
        }
        bx1[t]=x1; by1[t]=y1; bx2[t]=x2; by2[t]=y2;
        keepA[t] = valid ? 1 : 0;
        if (valid) {
            int ccx = min(31, max(0, (int)floorf((x1+x2)*0.5f*CELL_INV)));
            int ccy = min(31, max(0, (int)floorf((y1+y2)*0.5f*CELL_INV)));
            atomicAdd(&cellcnt[ccy*32 + ccx], 1u);
        }
    }
    __syncthreads();

    // exclusive scan over 1024 cells -> cstart; cellcnt becomes scatter cursor
    {
        unsigned orig = cellcnt[tid];
        unsigned x = orig;
        int lane = tid & 31, wid = tid >> 5;
        for (int o = 1; o < 32; o <<= 1) {
            unsigned y = __shfl_up_sync(0xffffffffu, x, o);
            if (lane >= o) x += y;
        }
        if (lane == 31) wsum[wid] = x;
        __syncthreads();
        if (wid == 0) {
            unsigned s = wsum[lane];
            for (int o = 1; o < 32; o <<= 1) {
                unsigned y = __shfl_up_sync(0xffffffffu, s, o);
                if (lane >= o) s += y;
            }
            wsum[lane] = s;
        }
        __syncthreads();
        unsigned incl = x + (wid > 0 ? wsum[wid-1] : 0u);
        unsigned excl = incl - orig;
        cstart[tid] = (unsigned short)excl;
        if (tid == NCELL_-1) cstart[NCELL_] = (unsigned short)incl;
        __syncthreads();
        cellcnt[tid] = excl;
    }
    __syncthreads();

    // scatter boxes into cell-sorted list
    for (int t = tid; t < K_; t += 1024) {
        if (keepA[t]) {
            int ccx = min(31, max(0, (int)floorf((bx1[t]+bx2[t])*0.5f*CELL_INV)));
            int ccy = min(31, max(0, (int)floorf((by1[t]+by2[t])*0.5f*CELL_INV)));
            unsigned p = atomicAdd(&cellcnt[ccy*32 + ccx], 1u);
            list[p] = (unsigned short)t;
        }
    }
    __syncthreads();

    // sparse edge detection: pairs (i<j) with IoU > 0.5, via 3x3 cell neighborhood
    for (int t = tid; t < K_; t += 1024) {
        if (!keepA[t]) continue;
        float jx1=bx1[t], jy1=by1[t], jx2=bx2[t], jy2=by2[t];
        float aj = (jx2-jx1)*(jy2-jy1);
        int ccx = min(31, max(0, (int)floorf((jx1+jx2)*0.5f*CELL_INV)));
        int ccy = min(31, max(0, (int)floorf((jy1+jy2)*0.5f*CELL_INV)));
        int gy0 = max(ccy-1,0), gy1 = min(ccy+1,31);
        int gx0 = max(ccx-1,0), gx1 = min(ccx+1,31);
        for (int gy = gy0; gy <= gy1; gy++)
        for (int gx = gx0; gx <= gx1; gx++) {
            int c = gy*32 + gx;
            int pe = cstart[c+1];
            for (int p = cstart[c]; p < pe; p++) {
                int i = list[p];
                if (i >= t) continue;
                float xx1 = fmaxf(bx1[i], jx1);
                float yy1 = fmaxf(by1[i], jy1);
                float xx2 = fminf(bx2[i], jx2);
                float yy2 = fminf(by2[i], jy2);
                float iw2 = xx2 - xx1, ih2 = yy2 - yy1;
                if (iw2 <= 0.f || ih2 <= 0.f) continue;
                float inter = iw2 * ih2;
                float ai = (bx2[i]-bx1[i])*(by2[i]-by1[i]);
                float iou = inter / (ai + aj - inter + 1e-12f);
                if (iou > 0.5f) {
                    int e = atomicAdd(&sE, 1);
                    if (e < EMAX_) edges[e] = ((unsigned)t << 16) | (unsigned)i;
                }
            }
        }
    }
    __syncthreads();

    // exact greedy resolve: process edges sorted ascending by target j
    if (tid == 0) {
        int E = sE; if (E > EMAX_) E = EMAX_;
        for (int a = 1; a < E; a++) {            // insertion sort (E is tiny)
            unsigned v = edges[a]; int q = a - 1;
            while (q >= 0 && edges[q] > v) { edges[q+1] = edges[q]; q--; }
            edges[q+1] = v;
        }
        for (int e = 0; e < E; e++) {
            int j = (int)(edges[e] >> 16), i = (int)(edges[e] & 0xffffu);
            if (keepA[i]) keepA[j] = 0;          // keep[j] &= !(suppress & keep[i])
        }
    }
    __syncthreads();

    // write outputs: scores[B,K] ++ bboxes[B,K,4] ++ keep[B,K]  (all f32)
    const int so = 0, bo = B_*K_, ko = B_*K_*5;
    for (int t = tid; t < K_; t += 1024) {
        unsigned long long key = g_topk[b][t];
        float val = __uint_as_float((unsigned)(key >> 32));
        bool kp = keepA[t] != 0;
        int g = b*K_ + t;
        if (so + g < out_size) out[so + g] = kp ? val : 0.f;
        if (bo + g*4 + 3 < out_size) {
            out[bo + g*4 + 0] = kp ? bx1[t] : 0.f;
            out[bo + g*4 + 1] = kp ? by1[t] : 0.f;
            out[bo + g*4 + 2] = kp ? bx2[t] : 0.f;
            out[bo + g*4 + 3] = kp ? by2[t] : 0.f;
        }
        if (ko + g < out_size) out[ko + g] = kp ? 1.f : 0.f;
    }
}

// ---------------- launch ----------------
extern "C" void kernel_launch(void* const* d_in, const int* in_sizes, int n_in,
                              void* d_out, int out_size) {
    (void)in_sizes; (void)n_in;
    const float* scores = (const float*)d_in[0];
    const float* deltas = (const float*)d_in[1];
    const float* sizes  = (const float*)d_in[2];
    const int* p_stride = (const int*)d_in[3];
    const int* p_offy   = (const int*)d_in[4];
    const int* p_offx   = (const int*)d_in[5];

    k_reset<<<1, 32>>>();
    dim3 g1(H_, B_);
    k_cand<<<g1, 256>>>(scores);
    k_topk<<<B_, 1024>>>();
    k_nms<<<B_, 1024>>>(deltas, sizes, p_stride, p_offy, p_offx,
                        (float*)d_out, out_size);
}

// round 3
// speedup vs baseline: 2.5220x; 2.5220x over previous
#include <cuda_runtime.h>
#include <cstdint>

#define B_ 8
#define H_ 1024
#define W_ 1024
#define HW_ (H_*W_)
#define K_ 2048
#define CAP_ 262144
#define SURV_ 4096
#define NBIN_ 2048
#define NCELL_ 1024   /* 32x32 grid */
#define CELL_INV (1.0f/256.0f)
#define EMAX_ 512
#define RPB_ 4        /* rows per block in k_cand */
#define SBUF_ 2048    /* per-block candidate staging */

// ---------------- scratch (static device memory only) ----------------
__device__ unsigned long long g_cand[B_][CAP_];
__device__ int g_cnt[B_];
__device__ unsigned long long g_surv[B_][SURV_];
__device__ int g_m[B_];
__device__ unsigned long long g_topk[B_][K_];
__device__ float4 g_box[B_][K_];

// ---------------- K0: reset counters ----------------
__global__ void k_reset() {
    if (threadIdx.x < B_) g_cnt[threadIdx.x] = 0;
}

// ---------------- K1: local-max candidates (block-aggregated) ----------------
// block = 4 image rows (256 threads x 4 px), grid = (H/4, B)
__global__ void __launch_bounds__(256) k_cand(const float* __restrict__ sc) {
    const int b = blockIdx.y, h0 = blockIdx.x * RPB_;
    const int w0 = threadIdx.x * 4;
    const int tid = threadIdx.x;
    const float NI = -__int_as_float(0x7f800000); // -inf

    __shared__ int scnt;
    __shared__ int sbase;
    __shared__ unsigned long long sbuf[SBUF_];
    if (tid == 0) scnt = 0;
    __syncthreads();

    float ra[6], rb[6], rc6[6];

    #define LOADROW(hh, v) do {                                             \
        int _h = (hh);                                                      \
        if (_h < 0 || _h >= H_) {                                           \
            v[0]=NI; v[1]=NI; v[2]=NI; v[3]=NI; v[4]=NI; v[5]=NI;           \
        } else {                                                            \
            const float* _r = sc + ((size_t)b * H_ + _h) * W_;              \
            float4 _m = *reinterpret_cast<const float4*>(_r + w0);          \
            v[1]=_m.x; v[2]=_m.y; v[3]=_m.z; v[4]=_m.w;                     \
            v[0] = (w0 > 0)       ? _r[w0-1] : NI;                          \
            v[5] = (w0 + 4 < W_)  ? _r[w0+4] : NI;                          \
        }                                                                   \
    } while (0)

    LOADROW(h0 - 1, ra);
    LOADROW(h0,     rb);

    #pragma unroll
    for (int r = 0; r < RPB_; r++) {
        LOADROW(h0 + r + 1, rc6);
        #pragma unroll
        for (int p = 0; p < 4; p++) {
            float s = rb[p+1];
            float nb = fmaxf(fmaxf(rb[p], rb[p+2]),
                       fmaxf(fmaxf(fmaxf(ra[p], ra[p+1]), ra[p+2]),
                             fmaxf(fmaxf(rc6[p], rc6[p+1]), rc6[p+2])));
            if (s > 0.5f && s >= nb) {   // s == 3x3 maxpool
                int pos = atomicAdd(&scnt, 1);
                if (pos < SBUF_) {
                    unsigned idx = (unsigned)((h0 + r) * W_ + w0 + p);
                    unsigned sb = __float_as_uint(s);
                    sbuf[pos] = ((unsigned long long)sb << 32) | (unsigned)(~idx);
                }
            }
        }
        #pragma unroll
        for (int q = 0; q < 6; q++) { ra[q] = rb[q]; rb[q] = rc6[q]; }
    }
    __syncthreads();

    int c = scnt < SBUF_ ? scnt : SBUF_;
    if (tid == 0) sbase = atomicAdd(&g_cnt[b], c);
    __syncthreads();
    int base = sbase;
    for (int i = tid; i < c; i += 256) {
        int pos = base + i;
        if (pos < CAP_) g_cand[b][pos] = sbuf[i];
    }
    #undef LOADROW
}

// ---------------- K2a: per-batch threshold selection + survivor compaction ----------------
__global__ void __launch_bounds__(1024) k_sel() {
    const int b = blockIdx.x, tid = threadIdx.x;
    __shared__ unsigned hist[NBIN_];
    __shared__ int sT, sW;

    int n = g_cnt[b]; if (n > CAP_) n = CAP_;
    hist[tid] = 0; hist[tid + 1024] = 0;
    if (tid == 0) { sT = 0; sW = 0; }
    __syncthreads();

    // histogram on top-11 mantissa bits (scores in (0.5,1) -> fixed exponent)
    for (int i = tid; i < n; i += 1024) {
        unsigned bits = (unsigned)(g_cand[b][i] >> 32);
        atomicAdd(&hist[(bits >> 12) & (NBIN_-1)], 1u);
    }
    __syncthreads();

    // inclusive suffix sums: hist[i] = #candidates with bin >= i
    for (int off = 1; off < NBIN_; off <<= 1) {
        unsigned v0 = hist[tid]      + ((tid + off        < NBIN_) ? hist[tid + off]        : 0u);
        unsigned v1 = hist[tid+1024] + ((tid + 1024 + off < NBIN_) ? hist[tid + 1024 + off] : 0u);
        __syncthreads();
        hist[tid] = v0; hist[tid + 1024] = v1;
        __syncthreads();
    }

    // threshold bin T: largest bin with suffix >= K
    for (int i = tid; i < NBIN_; i += 1024) {
        unsigned sfx = hist[i];
        unsigned nxt = (i + 1 < NBIN_) ? hist[i+1] : 0u;
        if (sfx >= K_ && nxt < K_) sT = i;
    }
    __syncthreads();
    int T = sT;

    // compact survivors (bin >= T) to gmem
    for (int i = tid; i < n; i += 1024) {
        unsigned long long key = g_cand[b][i];
        unsigned bits = (unsigned)(key >> 32);
        if ((int)((bits >> 12) & (NBIN_-1)) >= T) {
            int p = atomicAdd(&sW, 1);
            if (p < SURV_) g_surv[b][p] = key;
        }
    }
    // zero-fill topk (invalid marker)
    for (int i = tid; i < K_; i += 1024) g_topk[b][i] = 0ull;
    __syncthreads();
    if (tid == 0) g_m[b] = sW < SURV_ ? sW : SURV_;
}

// ---------------- K2b: exact rank computation + scatter (chip-parallel) ----------------
// grid = (32, B), block = 128. rank(key) = #{keys > key}; keys unique.
__global__ void __launch_bounds__(128) k_rank() {
    const int b = blockIdx.y, tid = threadIdx.x;
    const int s = blockIdx.x * 128 + tid;
    __shared__ __align__(16) unsigned long long sk[SURV_ + 8];

    int M = g_m[b];
    if (blockIdx.x * 128 >= M) return;

    for (int i = tid; i < M; i += 128) sk[i] = g_surv[b][i];
    if (tid < 8) sk[M + tid] = 0ull;   // pad (0 compares as not-greater)
    __syncthreads();

    if (s < M) {
        unsigned long long k = sk[s];
        int rank = 0;
        int Mp = (M + 7) & ~7;
        #pragma unroll 4
        for (int m = 0; m < Mp; m += 2) {
            ulonglong2 v = *reinterpret_cast<const ulonglong2*>(&sk[m]);
            rank += (v.x > k) + (v.y > k);
        }
        if (rank < K_) g_topk[b][rank] = k;
    }
}

// ---------------- K3a: box decode (chip-parallel gathers) ----------------
__global__ void __launch_bounds__(256) k_decode(
    const float* __restrict__ deltas, const float* __restrict__ sizes,
    const int* __restrict__ p_stride, const int* __restrict__ p_offy,
    const int* __restrict__ p_offx)
{
    int g = blockIdx.x * 256 + threadIdx.x;
    int b = g >> 11, t = g & (K_-1);
    unsigned long long key = g_topk[b][t];
    float4 box = make_float4(0.f, 0.f, 0.f, 0.f);
    if (key != 0ull) {
        const int stride = *p_stride, offy = *p_offy, offx = *p_offx;
        unsigned idx = ~(unsigned)key;
        int iw = (int)(idx & (W_-1)), ih = (int)(idx >> 10);
        float dx = deltas[((size_t)b*2 + 0)*HW_ + idx];
        float dy = deltas[((size_t)b*2 + 1)*HW_ + idx];
        float sx = sizes [((size_t)b*2 + 0)*HW_ + idx];
        float sy = sizes [((size_t)b*2 + 1)*HW_ + idx];
        float cx = (float)(iw*stride + offx) + dx;
        float cy = (float)(ih*stride + offy) + dy;
        box.x = cx - sx*0.5f; box.y = cy - sy*0.5f;
        box.z = cx + sx*0.5f; box.w = cy + sy*0.5f;
    }
    g_box[b][t] = box;
}

// ---------------- K3b: sparse-edge greedy NMS + outputs ----------------
__global__ void __launch_bounds__(1024) k_nms(float* __restrict__ out, int out_size)
{
    const int b = blockIdx.x, tid = threadIdx.x;
    __shared__ float bx1[K_], by1[K_], bx2[K_], by2[K_];   // 32 KB
    __shared__ unsigned cellcnt[NCELL_];
    __shared__ unsigned short cstart[NCELL_ + 2];
    __shared__ unsigned short list[K_];
    __shared__ unsigned char keepA[K_];
    __shared__ unsigned edges[EMAX_];
    __shared__ unsigned wsum[32];
    __shared__ int sE;

    if (tid == 0) sE = 0;
    cellcnt[tid] = 0;
    __syncthreads();

    // load boxes (coalesced) + bin into cells
    for (int t = tid; t < K_; t += 1024) {
        unsigned long long key = g_topk[b][t];
        float4 box = g_box[b][t];
        bool valid = key != 0ull;
        bx1[t]=box.x; by1[t]=box.y; bx2[t]=box.z; by2[t]=box.w;
        keepA[t] = valid ? 1 : 0;
        if (valid) {
            int ccx = min(31, max(0, (int)floorf((box.x+box.z)*0.5f*CELL_INV)));
            int ccy = min(31, max(0, (int)floorf((box.y+box.w)*0.5f*CELL_INV)));
            atomicAdd(&cellcnt[ccy*32 + ccx], 1u);
        }
    }
    __syncthreads();

    // exclusive scan over 1024 cells -> cstart; cellcnt becomes scatter cursor
    {
        unsigned orig = cellcnt[tid];
        unsigned x = orig;
        int lane = tid & 31, wid = tid >> 5;
        for (int o = 1; o < 32; o <<= 1) {
            unsigned y = __shfl_up_sync(0xffffffffu, x, o);
            if (lane >= o) x += y;
        }
        if (lane == 31) wsum[wid] = x;
        __syncthreads();
        if (wid == 0) {
            unsigned s2 = wsum[lane];
            for (int o = 1; o < 32; o <<= 1) {
                unsigned y = __shfl_up_sync(0xffffffffu, s2, o);
                if (lane >= o) s2 += y;
            }
            wsum[lane] = s2;
        }
        __syncthreads();
        unsigned incl = x + (wid > 0 ? wsum[wid-1] : 0u);
        unsigned excl = incl - orig;
        cstart[tid] = (unsigned short)excl;
        if (tid == NCELL_-1) cstart[NCELL_] = (unsigned short)incl;
        __syncthreads();
        cellcnt[tid] = excl;
    }
    __syncthreads();

    // scatter boxes into cell-sorted list
    for (int t = tid; t < K_; t += 1024) {
        if (keepA[t]) {
            int ccx = min(31, max(0, (int)floorf((bx1[t]+bx2[t])*0.5f*CELL_INV)));
            int ccy = min(31, max(0, (int)floorf((by1[t]+by2[t])*0.5f*CELL_INV)));
            unsigned p = atomicAdd(&cellcnt[ccy*32 + ccx], 1u);
            list[p] = (unsigned short)t;
        }
    }
    __syncthreads();

    // sparse edge detection: pairs (i<j) with IoU > 0.5 via 3x3 cell neighborhood
    for (int t = tid; t < K_; t += 1024) {
        if (!keepA[t]) continue;
        float jx1=bx1[t], jy1=by1[t], jx2=bx2[t], jy2=by2[t];
        float aj = (jx2-jx1)*(jy2-jy1);
        int ccx = min(31, max(0, (int)floorf((jx1+jx2)*0.5f*CELL_INV)));
        int ccy = min(31, max(0, (int)floorf((jy1+jy2)*0.5f*CELL_INV)));
        int gy0 = max(ccy-1,0), gy1 = min(ccy+1,31);
        int gx0 = max(ccx-1,0), gx1 = min(ccx+1,31);
        for (int gy = gy0; gy <= gy1; gy++)
        for (int gx = gx0; gx <= gx1; gx++) {
            int c = gy*32 + gx;
            int pe = cstart[c+1];
            for (int p = cstart[c]; p < pe; p++) {
                int i = list[p];
                if (i >= t) continue;
                float xx1 = fmaxf(bx1[i], jx1);
                float yy1 = fmaxf(by1[i], jy1);
                float xx2 = fminf(bx2[i], jx2);
                float yy2 = fminf(by2[i], jy2);
                float iw2 = xx2 - xx1, ih2 = yy2 - yy1;
                if (iw2 <= 0.f || ih2 <= 0.f) continue;
                float inter = iw2 * ih2;
                float ai = (bx2[i]-bx1[i])*(by2[i]-by1[i]);
                float iou = inter / (ai + aj - inter + 1e-12f);
                if (iou > 0.5f) {
                    int e = atomicAdd(&sE, 1);
                    if (e < EMAX_) edges[e] = ((unsigned)t << 16) | (unsigned)i;
                }
            }
        }
    }
    __syncthreads();

    // exact greedy resolve: edges sorted ascending by suppressed index j
    if (tid == 0) {
        int E = sE; if (E > EMAX_) E = EMAX_;
        for (int a = 1; a < E; a++) {
            unsigned v = edges[a]; int q = a - 1;
            while (q >= 0 && edges[q] > v) { edges[q+1] = edges[q]; q--; }
            edges[q+1] = v;
        }
        for (int e = 0; e < E; e++) {
            int j = (int)(edges[e] >> 16), i = (int)(edges[e] & 0xffffu);
            if (keepA[i]) keepA[j] = 0;
        }
    }
    __syncthreads();

    // outputs: scores[B,K] ++ bboxes[B,K,4] ++ keep[B,K]
    const int so = 0, bo = B_*K_, ko = B_*K_*5;
    for (int t = tid; t < K_; t += 1024) {
        unsigned long long key = g_topk[b][t];
        float val = __uint_as_float((unsigned)(key >> 32));
        bool kp = keepA[t] != 0;
        int g = b*K_ + t;
        if (so + g < out_size) out[so + g] = kp ? val : 0.f;
        if (bo + g*4 + 3 < out_size) {
            out[bo + g*4 + 0] = kp ? bx1[t] : 0.f;
            out[bo + g*4 + 1] = kp ? by1[t] : 0.f;
            out[bo + g*4 + 2] = kp ? bx2[t] : 0.f;
            out[bo + g*4 + 3] = kp ? by2[t] : 0.f;
        }
        if (ko + g < out_size) out[ko + g] = kp ? 1.f : 0.f;
    }
}

// ---------------- launch ----------------
extern "C" void kernel_launch(void* const* d_in, const int* in_sizes, int n_in,
                              void* d_out, int out_size) {
    (void)in_sizes; (void)n_in;
    const float* scores = (const float*)d_in[0];
    const float* deltas = (const float*)d_in[1];
    const float* sizes  = (const float*)d_in[2];
    const int* p_stride = (const int*)d_in[3];
    const int* p_offy   = (const int*)d_in[4];
    const int* p_offx   = (const int*)d_in[5];

    k_reset<<<1, 32>>>();
    dim3 g1(H_ / RPB_, B_);
    k_cand<<<g1, 256>>>(scores);
    k_sel<<<B_, 1024>>>();
    dim3 g2(SURV_ / 128, B_);
    k_rank<<<g2, 128>>>();
    k_decode<<<(B_ * K_) / 256, 256>>>(deltas, sizes, p_stride, p_offy, p_offx);
    k_nms<<<B_, 1024>>>((float*)d_out, out_size);
}

// round 7
// speedup vs baseline: 3.3657x; 1.3345x over previous
#include <cuda_runtime.h>
#include <cstdint>

#define B_ 8
#define H_ 1024
#define W_ 1024
#define HW_ (H_*W_)
#define K_ 2048
#define CAP_ 262144
#define SURV_ 4096
#define NBIN_ 2048
#define NCELL_ 1024   /* 32x32 grid */
#define CELL_INV (1.0f/256.0f)
#define EMAX_ 512
#define RPB_ 8        /* rows per block in k_cand */
#define SBUF_ 2048    /* per-block candidate staging */

// ---------------- scratch (static device memory only) ----------------
__device__ unsigned long long g_cand[B_][CAP_];
__device__ int g_cnt[B_];
__device__ unsigned g_hist[B_][NBIN_];
__device__ int g_T[B_];
__device__ unsigned g_base[B_][NBIN_];    // seg start = #keys in higher bins
__device__ unsigned g_segend[B_][NBIN_];  // seg end   = #keys in bins >= bin
__device__ unsigned g_cur[B_][NBIN_];     // scatter cursors
__device__ unsigned long long g_surv[B_][SURV_];
__device__ int g_m[B_];
__device__ unsigned long long g_topk[B_][K_];
__device__ float4 g_box[B_][K_];

// ---------------- K0: zero counters + histograms ----------------
__global__ void k_reset() {
    int g = blockIdx.x * 1024 + threadIdx.x;
    if (g < B_ * NBIN_) ((unsigned*)g_hist)[g] = 0u;
    if (g < B_) g_cnt[g] = 0;
}

// ---------------- K1: local-max candidates + histogram (block-aggregated) ----------------
// block = 8 image rows (256 threads x 4 px), grid = (H/8, B)
__global__ void __launch_bounds__(256) k_cand(const float* __restrict__ sc) {
    const int b = blockIdx.y, h0 = blockIdx.x * RPB_;
    const int tid = threadIdx.x;
    const int w0 = tid * 4;
    const int lane = tid & 31;
    const float NI = -__int_as_float(0x7f800000); // -inf

    __shared__ int scnt;
    __shared__ int sbase;
    __shared__ unsigned long long sbuf[SBUF_];
    __shared__ unsigned shist[NBIN_];
    for (int i = tid; i < NBIN_; i += 256) shist[i] = 0u;
    if (tid == 0) scnt = 0;
    __syncthreads();

    float ra[6], rb[6], rc6[6];

    #define LOADROW(hh, v) do {                                             \
        int _h = (hh);                                                      \
        if ((unsigned)_h >= (unsigned)H_) {                                 \
            v[0]=NI; v[1]=NI; v[2]=NI; v[3]=NI; v[4]=NI; v[5]=NI;           \
        } else {                                                            \
            const float* _r = sc + ((size_t)b * H_ + _h) * W_;              \
            float4 _m = *reinterpret_cast<const float4*>(_r + w0);          \
            float _lw = __shfl_up_sync(0xffffffffu, _m.w, 1);               \
            float _rx = __shfl_down_sync(0xffffffffu, _m.x, 1);             \
            v[1]=_m.x; v[2]=_m.y; v[3]=_m.z; v[4]=_m.w;                     \
            v[0] = lane        ? _lw : ((w0 > 0)      ? _r[w0-1] : NI);     \
            v[5] = (lane != 31)? _rx : ((w0 + 4 < W_) ? _r[w0+4] : NI);     \
        }                                                                   \
    } while (0)

    LOADROW(h0 - 1, ra);
    LOADROW(h0,     rb);

    #pragma unroll
    for (int r = 0; r < RPB_; r++) {
        LOADROW(h0 + r + 1, rc6);
        #pragma unroll
        for (int p = 0; p < 4; p++) {
            float s = rb[p+1];
            float nb = fmaxf(fmaxf(rb[p], rb[p+2]),
                       fmaxf(fmaxf(fmaxf(ra[p], ra[p+1]), ra[p+2]),
                             fmaxf(fmaxf(rc6[p], rc6[p+1]), rc6[p+2])));
            if (s > 0.5f && s >= nb) {   // s == 3x3 maxpool
                int pos = atomicAdd(&scnt, 1);
                if (pos < SBUF_) {
                    unsigned idx = (unsigned)((h0 + r) * W_ + w0 + p);
                    unsigned sb = __float_as_uint(s);
                    sbuf[pos] = ((unsigned long long)sb << 32) | (unsigned)(~idx);
                    atomicAdd(&shist[(sb >> 12) & (NBIN_-1)], 1u);
                }
            }
        }
        #pragma unroll
        for (int q = 0; q < 6; q++) { ra[q] = rb[q]; rb[q] = rc6[q]; }
    }
    __syncthreads();

    int c = scnt < SBUF_ ? scnt : SBUF_;
    if (tid == 0) sbase = atomicAdd(&g_cnt[b], c);
    // flush non-zero histogram bins
    for (int i = tid; i < NBIN_; i += 256) {
        unsigned v = shist[i];
        if (v) atomicAdd(&g_hist[b][i], v);
    }
    __syncthreads();
    int base = sbase;
    for (int i = tid; i < c; i += 256) {
        int pos = base + i;
        if (pos < CAP_) g_cand[b][pos] = sbuf[i];
    }
    #undef LOADROW
}

// ---------------- K2a: per-batch suffix scan -> threshold + per-bin bases ----------------
__global__ void __launch_bounds__(1024) k_thresh() {
    const int b = blockIdx.x, tid = threadIdx.x;
    __shared__ unsigned sfx[NBIN_];
    __shared__ int sT;

    sfx[tid] = g_hist[b][tid]; sfx[tid + 1024] = g_hist[b][tid + 1024];
    if (tid == 0) sT = 0;
    __syncthreads();

    // inclusive suffix sums: sfx[i] = #candidates with bin >= i
    for (int off = 1; off < NBIN_; off <<= 1) {
        unsigned v0 = sfx[tid]      + ((tid + off        < NBIN_) ? sfx[tid + off]        : 0u);
        unsigned v1 = sfx[tid+1024] + ((tid + 1024 + off < NBIN_) ? sfx[tid + 1024 + off] : 0u);
        __syncthreads();
        sfx[tid] = v0; sfx[tid + 1024] = v1;
        __syncthreads();
    }

    // threshold bin T: largest bin with suffix >= K
    for (int i = tid; i < NBIN_; i += 1024) {
        unsigned s = sfx[i];
        unsigned nx = (i + 1 < NBIN_) ? sfx[i+1] : 0u;
        if (s >= K_ && nx < K_) sT = i;
    }
    __syncthreads();
    int T = sT;

    for (int i = tid; i < NBIN_; i += 1024) {
        unsigned base = (i + 1 < NBIN_) ? sfx[i+1] : 0u;
        g_base[b][i] = base;
        g_segend[b][i] = sfx[i];
        g_cur[b][i] = base;
    }
    if (tid == 0) {
        unsigned M = sfx[T];
        g_m[b] = (int)(M < SURV_ ? M : SURV_);
        g_T[b] = T;
    }
    for (int i = tid; i < K_; i += 1024) g_topk[b][i] = 0ull;
}

// ---------------- K2b: chip-wide bin-grouped compaction ----------------
// grid = (64, B), 256 threads; block i covers candidate slots [i*4096, (i+1)*4096)
__global__ void __launch_bounds__(256) k_compact() {
    const int b = blockIdx.y;
    int n = g_cnt[b]; if (n > CAP_) n = CAP_;
    int start = blockIdx.x * 4096;
    if (start >= n) return;
    int end = start + 4096; if (end > n) end = n;
    const int T = g_T[b];
    for (int i = start + threadIdx.x; i < end; i += 256) {
        unsigned long long key = g_cand[b][i];
        int bin = (int)((unsigned)(key >> 44) & (NBIN_-1));
        if (bin >= T) {
            unsigned pos = atomicAdd(&g_cur[b][bin], 1u);
            if (pos < SURV_) g_surv[b][pos] = key;
        }
    }
}

// ---------------- K2c: exact rank within bin segment + scatter ----------------
// grid = (16, B), 256 threads; keys unique -> ranks collision-free
__global__ void __launch_bounds__(256) k_rank() {
    const int b = blockIdx.y;
    const int p = blockIdx.x * 256 + threadIdx.x;
    const int M = g_m[b];
    if (blockIdx.x * 256 >= M) return;
    if (p >= M) return;

    unsigned long long key = g_surv[b][p];
    int bin = (int)((unsigned)(key >> 44) & (NBIN_-1));
    int s0 = (int)g_base[b][bin];
    int e  = (int)g_segend[b][bin];
    if (e > SURV_) e = SURV_;

    int rank = s0;
    const unsigned long long* seg = g_surv[b];
    int m = s0;
    #pragma unroll 1
    for (; m + 4 <= e; m += 4) {
        rank += (seg[m]   > key);
        rank += (seg[m+1] > key);
        rank += (seg[m+2] > key);
        rank += (seg[m+3] > key);
    }
    for (; m < e; m++) rank += (seg[m] > key);

    if (rank < K_) g_topk[b][rank] = key;
}

// ---------------- K3a: box decode (chip-parallel gathers) ----------------
__global__ void __launch_bounds__(256) k_decode(
    const float* __restrict__ deltas, const float* __restrict__ sizes,
    const int* __restrict__ p_stride, const int* __restrict__ p_offy,
    const int* __restrict__ p_offx)
{
    int g = blockIdx.x * 256 + threadIdx.x;
    int b = g >> 11, t = g & (K_-1);
    unsigned long long key = g_topk[b][t];
    float4 box = make_float4(0.f, 0.f, 0.f, 0.f);
    if (key != 0ull) {
        const int stride = *p_stride, offy = *p_offy, offx = *p_offx;
        unsigned idx = ~(unsigned)key;
        int iw = (int)(idx & (W_-1)), ih = (int)(idx >> 10);
        float dx = deltas[((size_t)b*2 + 0)*HW_ + idx];
        float dy = deltas[((size_t)b*2 + 1)*HW_ + idx];
        float sx = sizes [((size_t)b*2 + 0)*HW_ + idx];
        float sy = sizes [((size_t)b*2 + 1)*HW_ + idx];
        float cx = (float)(iw*stride + offx) + dx;
        float cy = (float)(ih*stride + offy) + dy;
        box.x = cx - sx*0.5f; box.y = cy - sy*0.5f;
        box.z = cx + sx*0.5f; box.w = cy + sy*0.5f;
    }
    g_box[b][t] = box;
}

// ---------------- K3b: sparse-edge greedy NMS + outputs ----------------
__global__ void __launch_bounds__(1024) k_nms(float* __restrict__ out, int out_size)
{
    const int b = blockIdx.x, tid = threadIdx.x;
    __shared__ float bx1[K_], by1[K_], bx2[K_], by2[K_];   // 32 KB
    __shared__ unsigned cellcnt[NCELL_];
    __shared__ unsigned short cstart[NCELL_ + 2];
    __shared__ unsigned short list[K_];
    __shared__ unsigned short cellof[K_];
    __shared__ unsigned char keepA[K_];
    __shared__ unsigned edges[EMAX_];
    __shared__ unsigned wsum[32];
    __shared__ int sE;

    if (tid == 0) sE = 0;
    cellcnt[tid] = 0;
    __syncthreads();

    // load boxes (coalesced) + bin into cells
    for (int t = tid; t < K_; t += 1024) {
        unsigned long long key = g_topk[b][t];
        float4 box = g_box[b][t];
        bool valid = key != 0ull;
        bx1[t]=box.x; by1[t]=box.y; bx2[t]=box.z; by2[t]=box.w;
        keepA[t] = valid ? 1 : 0;
        unsigned short cell = 0;
        if (valid) {
            int ccx = min(31, max(0, (int)floorf((box.x+box.z)*0.5f*CELL_INV)));
            int ccy = min(31, max(0, (int)floorf((box.y+box.w)*0.5f*CELL_INV)));
            cell = (unsigned short)(ccy*32 + ccx);
            atomicAdd(&cellcnt[cell], 1u);
        }
        cellof[t] = cell;
    }
    __syncthreads();

    // exclusive scan over 1024 cells -> cstart; cellcnt becomes scatter cursor
    {
        unsigned orig = cellcnt[tid];
        unsigned x = orig;
        int lane = tid & 31, wid = tid >> 5;
        for (int o = 1; o < 32; o <<= 1) {
            unsigned y = __shfl_up_sync(0xffffffffu, x, o);
            if (lane >= o) x += y;
        }
        if (lane == 31) wsum[wid] = x;
        __syncthreads();
        if (wid == 0) {
            unsigned s2 = wsum[lane];
            for (int o = 1; o < 32; o <<= 1) {
                unsigned y = __shfl_up_sync(0xffffffffu, s2, o);
                if (lane >= o) s2 += y;
            }
            wsum[lane] = s2;
        }
        __syncthreads();
        unsigned incl = x + (wid > 0 ? wsum[wid-1] : 0u);
        unsigned excl = incl - orig;
        cstart[tid] = (unsigned short)excl;
        if (tid == NCELL_-1) cstart[NCELL_] = (unsigned short)incl;
        __syncthreads();
        cellcnt[tid] = excl;
    }
    __syncthreads();

    // scatter boxes into cell-sorted list
    for (int t = tid; t < K_; t += 1024) {
        if (keepA[t]) {
            unsigned p = atomicAdd(&cellcnt[cellof[t]], 1u);
            list[p] = (unsigned short)t;
        }
    }
    __syncthreads();

    // sparse edge detection: pairs (i<j) with IoU > 0.5 via 3x3 cell neighborhood
    for (int t = tid; t < K_; t += 1024) {
        if (!keepA[t]) continue;
        float jx1=bx1[t], jy1=by1[t], jx2=bx2[t], jy2=by2[t];
        float aj = (jx2-jx1)*(jy2-jy1);
        int cc = cellof[t];
        int ccx = cc & 31, ccy = cc >> 5;
        int gy0 = max(ccy-1,0), gy1 = min(ccy+1,31);
        int gx0 = max(ccx-1,0), gx1 = min(ccx+1,31);
        for (int gy = gy0; gy <= gy1; gy++)
        for (int gx = gx0; gx <= gx1; gx++) {
            int c = gy*32 + gx;
            int pe = cstart[c+1];
            for (int p = cstart[c]; p < pe; p++) {
                int i = list[p];
                if (i >= t) continue;
                float xx1 = fmaxf(bx1[i], jx1);
                float yy1 = fmaxf(by1[i], jy1);
                float xx2 = fminf(bx2[i], jx2);
                float yy2 = fminf(by2[i], jy2);
                float iw2 = xx2 - xx1, ih2 = yy2 - yy1;
                if (iw2 <= 0.f || ih2 <= 0.f) continue;
                float inter = iw2 * ih2;
                float ai = (bx2[i]-bx1[i])*(by2[i]-by1[i]);
                float iou = inter / (ai + aj - inter + 1e-12f);
                if (iou > 0.5f) {
                    int e = atomicAdd(&sE, 1);
                    if (e < EMAX_) edges[e] = ((unsigned)t << 16) | (unsigned)i;
                }
            }
        }
    }
    __syncthreads();

    // exact greedy resolve: edges sorted ascending by suppressed index j
    if (tid == 0) {
        int E = sE; if (E > EMAX_) E = EMAX_;
        for (int a = 1; a < E; a++) {
            unsigned v = edges[a]; int q = a - 1;
            while (q >= 0 && edges[q] > v) { edges[q+1] = edges[q]; q--; }
            edges[q+1] = v;
        }
        for (int e = 0; e < E; e++) {
            int j = (int)(edges[e] >> 16), i = (int)(edges[e] & 0xffffu);
            if (keepA[i]) keepA[j] = 0;
        }
    }
    __syncthreads();

    // outputs: scores[B,K] ++ bboxes[B,K,4] ++ keep[B,K]
    const int so = 0, bo = B_*K_, ko = B_*K_*5;
    for (int t = tid; t < K_; t += 1024) {
        unsigned long long key = g_topk[b][t];
        float val = __uint_as_float((unsigned)(key >> 32));
        bool kp = keepA[t] != 0;
        int g = b*K_ + t;
        if (so + g < out_size) out[so + g] = kp ? val : 0.f;
        if (bo + g*4 + 3 < out_size) {
            out[bo + g*4 + 0] = kp ? bx1[t] : 0.f;
            out[bo + g*4 + 1] = kp ? by1[t] : 0.f;
            out[bo + g*4 + 2] = kp ? bx2[t] : 0.f;
            out[bo + g*4 + 3] = kp ? by2[t] : 0.f;
        }
        if (ko + g < out_size) out[ko + g] = kp ? 1.f : 0.f;
    }
}

// ---------------- launch ----------------
extern "C" void kernel_launch(void* const* d_in, const int* in_sizes, int n_in,
                              void* d_out, int out_size) {
    (void)in_sizes; (void)n_in;
    const float* scores = (const float*)d_in[0];
    const float* deltas = (const float*)d_in[1];
    const float* sizes  = (const float*)d_in[2];
    const int* p_stride = (const int*)d_in[3];
    const int* p_offy   = (const int*)d_in[4];
    const int* p_offx   = (const int*)d_in[5];

    k_reset<<<16, 1024>>>();
    dim3 g1(H_ / RPB_, B_);
    k_cand<<<g1, 256>>>(scores);
    k_thresh<<<B_, 1024>>>();
    dim3 gc(CAP_ / 4096, B_);
    k_compact<<<gc, 256>>>();
    dim3 gr(SURV_ / 256, B_);
    k_rank<<<gr, 256>>>();
    k_decode<<<(B_ * K_) / 256, 256>>>(deltas, sizes, p_stride, p_offy, p_offx);
    k_nms<<<B_, 1024>>>((float*)d_out, out_size);
}

// round 9
// speedup vs baseline: 3.5380x; 1.0512x over previous
#include <cuda_runtime.h>
#include <cstdint>

#define B_ 8
#define H_ 1024
#define W_ 1024
#define HW_ (H_*W_)
#define K_ 2048
#define SURV_ 4096
#define NBIN_ 2048
#define NBUCK_ 128
#define CAPB_ 8192
#define NCELL_ 1024   /* 32x32 grid */
#define CELL_INV (1.0f/256.0f)
#define EMAX_ 512
#define RPB_ 8        /* rows per block in k_cand */
#define SBUF_ 2048    /* per-block candidate staging */

// ---------------- scratch (static device memory only) ----------------
__device__ unsigned long long g_bcand[B_][NBUCK_][CAPB_];  // bucketed candidates
__device__ unsigned g_bcnt[B_][NBUCK_];
__device__ unsigned g_hist[B_][NBIN_];
__device__ int g_T[B_];
__device__ unsigned g_base[B_][NBIN_];    // seg start = #keys in higher bins
__device__ unsigned g_segend[B_][NBIN_];  // seg end   = #keys in bins >= bin
__device__ unsigned g_cur[B_][NBIN_];     // scatter cursors
__device__ unsigned long long g_surv[B_][SURV_];
__device__ int g_m[B_];
__device__ unsigned long long g_topk[B_][K_];
__device__ float4 g_box[B_][K_];

// ---------------- K0: zero histograms + bucket counters ----------------
__global__ void k_reset() {
    int g = blockIdx.x * 1024 + threadIdx.x;
    if (g < B_ * NBIN_) ((unsigned*)g_hist)[g] = 0u;
    if (g < B_ * NBUCK_) ((unsigned*)g_bcnt)[g] = 0u;
}

// ---------------- K1: local-max candidates (separable max9, bucketed emit) ----------------
// block = 8 image rows (256 threads x 4 px), grid = (H/8, B)
__global__ void __launch_bounds__(256) k_cand(const float* __restrict__ sc) {
    const int b = blockIdx.y, h0 = blockIdx.x * RPB_;
    const int tid = threadIdx.x;
    const int w0 = tid * 4;
    const int lane = tid & 31;
    const float NI = -__int_as_float(0x7f800000); // -inf

    __shared__ int scnt;
    __shared__ unsigned long long sbuf[SBUF_];
    __shared__ unsigned shist[NBIN_];
    __shared__ unsigned sbase[NBUCK_];
    __shared__ unsigned scur[NBUCK_];
    for (int i = tid; i < NBIN_; i += 256) shist[i] = 0u;
    if (tid < NBUCK_) scur[tid] = 0u;
    if (tid == 0) scnt = 0;
    __syncthreads();

    float v[6], ha[4], hb[4], hc[4], c0[4], cn[4];

    #define LOADROW(hh) do {                                                \
        int _h = (hh);                                                      \
        if ((unsigned)_h >= (unsigned)H_) {                                 \
            v[0]=NI; v[1]=NI; v[2]=NI; v[3]=NI; v[4]=NI; v[5]=NI;           \
        } else {                                                            \
            const float* _r = sc + ((size_t)b * H_ + _h) * W_;              \
            float4 _m = *reinterpret_cast<const float4*>(_r + w0);          \
            float _lw = __shfl_up_sync(0xffffffffu, _m.w, 1);               \
            float _rx = __shfl_down_sync(0xffffffffu, _m.x, 1);             \
            v[1]=_m.x; v[2]=_m.y; v[3]=_m.z; v[4]=_m.w;                     \
            v[0] = lane        ? _lw : ((w0 > 0)      ? _r[w0-1] : NI);     \
            v[5] = (lane != 31)? _rx : ((w0 + 4 < W_) ? _r[w0+4] : NI);     \
        }                                                                   \
    } while (0)
    // horizontal 3-max of loaded row
    #define HMAX(dst) do {                                                  \
        dst[0] = fmaxf(fmaxf(v[0], v[1]), v[2]);                            \
        dst[1] = fmaxf(fmaxf(v[1], v[2]), v[3]);                            \
        dst[2] = fmaxf(fmaxf(v[2], v[3]), v[4]);                            \
        dst[3] = fmaxf(fmaxf(v[3], v[4]), v[5]);                            \
    } while (0)

    LOADROW(h0 - 1); HMAX(ha);
    LOADROW(h0);     HMAX(hb); c0[0]=v[1]; c0[1]=v[2]; c0[2]=v[3]; c0[3]=v[4];

    #pragma unroll
    for (int r = 0; r < RPB_; r++) {
        LOADROW(h0 + r + 1); HMAX(hc); cn[0]=v[1]; cn[1]=v[2]; cn[2]=v[3]; cn[3]=v[4];
        #pragma unroll
        for (int p = 0; p < 4; p++) {
            float s = c0[p];
            float pooled = fmaxf(fmaxf(ha[p], hb[p]), hc[p]);  // includes center
            if (s > 0.5f && s == pooled) {                      // reference mask exactly
                int pos = atomicAdd(&scnt, 1);
                if (pos < SBUF_) {
                    unsigned idx = (unsigned)((h0 + r) * W_ + w0 + p);
                    unsigned sb = __float_as_uint(s);
                    sbuf[pos] = ((unsigned long long)sb << 32) | (unsigned)(~idx);
                    atomicAdd(&shist[(sb >> 12) & (NBIN_-1)], 1u);
                }
            }
        }
        #pragma unroll
        for (int q = 0; q < 4; q++) { ha[q]=hb[q]; hb[q]=hc[q]; c0[q]=cn[q]; }
    }
    __syncthreads();

    // per-bucket counts from fine histogram -> reserve global ranges
    if (tid < NBUCK_) {
        unsigned cnt = 0;
        #pragma unroll
        for (int q = 0; q < 16; q++) cnt += shist[tid * 16 + q];
        if (cnt) sbase[tid] = atomicAdd(&g_bcnt[b][tid], cnt);
    }
    // flush non-zero fine-histogram bins
    for (int i = tid; i < NBIN_; i += 256) {
        unsigned hv = shist[i];
        if (hv) atomicAdd(&g_hist[b][i], hv);
    }
    __syncthreads();

    int c = scnt < SBUF_ ? scnt : SBUF_;
    for (int i = tid; i < c; i += 256) {
        unsigned long long key = sbuf[i];
        int bu = (int)((unsigned)(key >> 48) & (NBUCK_-1));   // bin>>4
        unsigned pos = atomicAdd(&scur[bu], 1u) + sbase[bu];
        if (pos < CAPB_) g_bcand[b][bu][pos] = key;
    }
    #undef LOADROW
    #undef HMAX
}

// ---------------- K2a: per-batch suffix scan -> threshold + per-bin bases ----------------
__global__ void __launch_bounds__(1024) k_thresh() {
    const int b = blockIdx.x, tid = threadIdx.x;
    __shared__ unsigned sfx[NBIN_];
    __shared__ int sT;

    sfx[tid] = g_hist[b][tid]; sfx[tid + 1024] = g_hist[b][tid + 1024];
    if (tid == 0) sT = 0;
    __syncthreads();

    // inclusive suffix sums: sfx[i] = #candidates with bin >= i
    for (int off = 1; off < NBIN_; off <<= 1) {
        unsigned v0 = sfx[tid]      + ((tid + off        < NBIN_) ? sfx[tid + off]        : 0u);
        unsigned v1 = sfx[tid+1024] + ((tid + 1024 + off < NBIN_) ? sfx[tid + 1024 + off] : 0u);
        __syncthreads();
        sfx[tid] = v0; sfx[tid + 1024] = v1;
        __syncthreads();
    }

    // threshold bin T: largest bin with suffix >= K
    for (int i = tid; i < NBIN_; i += 1024) {
        unsigned s = sfx[i];
        unsigned nx = (i + 1 < NBIN_) ? sfx[i+1] : 0u;
        if (s >= K_ && nx < K_) sT = i;
    }
    __syncthreads();
    int T = sT;

    for (int i = tid; i < NBIN_; i += 1024) {
        unsigned base = (i + 1 < NBIN_) ? sfx[i+1] : 0u;
        g_base[b][i] = base;
        g_segend[b][i] = sfx[i];
        g_cur[b][i] = base;
    }
    if (tid == 0) {
        unsigned M = sfx[T];
        g_m[b] = (int)(M < SURV_ ? M : SURV_);
        g_T[b] = T;
    }
    for (int i = tid; i < K_; i += 1024) g_topk[b][i] = 0ull;
}

// ---------------- K2b: compaction from surviving buckets only ----------------
// grid = (NBUCK*4, B); 4 blocks share one bucket
__global__ void __launch_bounds__(256) k_compact() {
    const int b = blockIdx.y;
    const int bu = blockIdx.x >> 2, part = blockIdx.x & 3;
    const int T = g_T[b];
    if (bu < (T >> 4)) return;
    int cnt = (int)g_bcnt[b][bu]; if (cnt > CAPB_) cnt = CAPB_;
    int chunk = (cnt + 3) >> 2;
    int s = part * chunk, e = s + chunk; if (e > cnt) e = cnt;
    for (int i = s + threadIdx.x; i < e; i += 256) {
        unsigned long long key = g_bcand[b][bu][i];
        int bin = (int)((unsigned)(key >> 44) & (NBIN_-1));
        if (bin >= T) {
            unsigned pos = atomicAdd(&g_cur[b][bin], 1u);
            if (pos < SURV_) g_surv[b][pos] = key;
        }
    }
}

// ---------------- K2c: exact rank within bin segment + scatter + box decode ----------------
__global__ void __launch_bounds__(256) k_rank(
    const float* __restrict__ deltas, const float* __restrict__ sizes,
    const int* __restrict__ p_stride, const int* __restrict__ p_offy,
    const int* __restrict__ p_offx)
{
    const int b = blockIdx.y;
    const int p = blockIdx.x * 256 + threadIdx.x;
    const int M = g_m[b];
    if (blockIdx.x * 256 >= M) return;
    if (p >= M) return;

    unsigned long long key = g_surv[b][p];
    int bin = (int)((unsigned)(key >> 44) & (NBIN_-1));
    int s0 = (int)g_base[b][bin];
    int e  = (int)g_segend[b][bin];
    if (e > SURV_) e = SURV_;

    int rank = s0;
    const unsigned long long* seg = g_surv[b];
    int m = s0;
    #pragma unroll 1
    for (; m + 4 <= e; m += 4) {
        rank += (seg[m]   > key);
        rank += (seg[m+1] > key);
        rank += (seg[m+2] > key);
        rank += (seg[m+3] > key);
    }
    for (; m < e; m++) rank += (seg[m] > key);

    if (rank < K_) {
        g_topk[b][rank] = key;
        // decode box (exact reference op order)
        const int stride = *p_stride, offy = *p_offy, offx = *p_offx;
        unsigned idx = ~(unsigned)key;
        int iw = (int)(idx & (W_-1)), ih = (int)(idx >> 10);
        float dx = deltas[((size_t)b*2 + 0)*HW_ + idx];
        float dy = deltas[((size_t)b*2 + 1)*HW_ + idx];
        float sx = sizes [((size_t)b*2 + 0)*HW_ + idx];
        float sy = sizes [((size_t)b*2 + 1)*HW_ + idx];
        float cx = (float)(iw*stride + offx) + dx;
        float cy = (float)(ih*stride + offy) + dy;
        float4 box;
        box.x = cx - sx*0.5f; box.y = cy - sy*0.5f;
        box.z = cx + sx*0.5f; box.w = cy + sy*0.5f;
        g_box[b][rank] = box;
    }
}

// ---------------- K3: sparse-edge greedy NMS + outputs ----------------
__global__ void __launch_bounds__(1024) k_nms(float* __restrict__ out, int out_size)
{
    const int b = blockIdx.x, tid = threadIdx.x;
    __shared__ float bx1[K_], by1[K_], bx2[K_], by2[K_];   // 32 KB
    __shared__ unsigned cellcnt[NCELL_];
    __shared__ unsigned short cstart[NCELL_ + 2];
    __shared__ unsigned short list[K_];
    __shared__ unsigned short cellof[K_];
    __shared__ unsigned char keepA[K_];
    __shared__ unsigned edges[EMAX_];
    __shared__ unsigned wsum[32];
    __shared__ int sE;

    if (tid == 0) sE = 0;
    cellcnt[tid] = 0;
    __syncthreads();

    // load boxes (coalesced) + bin into cells
    for (int t = tid; t < K_; t += 1024) {
        unsigned long long key = g_topk[b][t];
        float4 box = g_box[b][t];
        bool valid = key != 0ull;
        if (!valid) { box.x=0.f; box.y=0.f; box.z=0.f; box.w=0.f; }
        bx1[t]=box.x; by1[t]=box.y; bx2[t]=box.z; by2[t]=box.w;
        keepA[t] = valid ? 1 : 0;
        unsigned short cell = 0;
        if (valid) {
            int ccx = min(31, max(0, (int)floorf((box.x+box.z)*0.5f*CELL_INV)));
            int ccy = min(31, max(0, (int)floorf((box.y+box.w)*0.5f*CELL_INV)));
            cell = (unsigned short)(ccy*32 + ccx);
            atomicAdd(&cellcnt[cell], 1u);
        }
        cellof[t] = cell;
    }
    __syncthreads();

    // exclusive scan over 1024 cells -> cstart; cellcnt becomes scatter cursor
    {
        unsigned orig = cellcnt[tid];
        unsigned x = orig;
        int lane = tid & 31, wid = tid >> 5;
        for (int o = 1; o < 32; o <<= 1) {
            unsigned y = __shfl_up_sync(0xffffffffu, x, o);
            if (lane >= o) x += y;
        }
        if (lane == 31) wsum[wid] = x;
        __syncthreads();
        if (wid == 0) {
            unsigned s2 = wsum[lane];
            for (int o = 1; o < 32; o <<= 1) {
                unsigned y = __shfl_up_sync(0xffffffffu, s2, o);
                if (lane >= o) s2 += y;
            }
            wsum[lane] = s2;
        }
        __syncthreads();
        unsigned incl = x + (wid > 0 ? wsum[wid-1] : 0u);
        unsigned excl = incl - orig;
        cstart[tid] = (unsigned short)excl;
        if (tid == NCELL_-1) cstart[NCELL_] = (unsigned short)incl;
        __syncthreads();
        cellcnt[tid] = excl;
    }
    __syncthreads();

    // scatter boxes into cell-sorted list
    for (int t = tid; t < K_; t += 1024) {
        if (keepA[t]) {
            unsigned p = atomicAdd(&cellcnt[cellof[t]], 1u);
            list[p] = (unsigned short)t;
        }
    }
    __syncthreads();

    // sparse edge detection: pairs (i<j) with IoU > 0.5 via 3x3 cell neighborhood
    for (int t = tid; t < K_; t += 1024) {
        if (!keepA[t]) continue;
        float jx1=bx1[t], jy1=by1[t], jx2=bx2[t], jy2=by2[t];
        float aj = (jx2-jx1)*(jy2-jy1);
        int cc = cellof[t];
        int ccx = cc & 31, ccy = cc >> 5;
        int gy0 = max(ccy-1,0), gy1 = min(ccy+1,31);
        int gx0 = max(ccx-1,0), gx1 = min(ccx+1,31);
        for (int gy = gy0; gy <= gy1; gy++)
        for (int gx = gx0; gx <= gx1; gx++) {
            int c = gy*32 + gx;
            int pe = cstart[c+1];
            for (int p = cstart[c]; p < pe; p++) {
                int i = list[p];
                if (i >= t) continue;
                float xx1 = fmaxf(bx1[i], jx1);
                float yy1 = fmaxf(by1[i], jy1);
                float xx2 = fminf(bx2[i], jx2);
                float yy2 = fminf(by2[i], jy2);
                float iw2 = xx2 - xx1, ih2 = yy2 - yy1;
                if (iw2 <= 0.f || ih2 <= 0.f) continue;
                float inter = iw2 * ih2;
                float ai = (bx2[i]-bx1[i])*(by2[i]-by1[i]);
                float iou = inter / (ai + aj - inter + 1e-12f);
                if (iou > 0.5f) {
                    int e = atomicAdd(&sE, 1);
                    if (e < EMAX_) edges[e] = ((unsigned)t << 16) | (unsigned)i;
                }
            }
        }
    }
    __syncthreads();

    // exact greedy resolve: edges sorted ascending by suppressed index j
    if (tid == 0) {
        int E = sE; if (E > EMAX_) E = EMAX_;
        for (int a = 1; a < E; a++) {
            unsigned v = edges[a]; int q = a - 1;
            while (q >= 0 && edges[q] > v) { edges[q+1] = edges[q]; q--; }
            edges[q+1] = v;
        }
        for (int e = 0; e < E; e++) {
            int j = (int)(edges[e] >> 16), i = (int)(edges[e] & 0xffffu);
            if (keepA[i]) keepA[j] = 0;
        }
    }
    __syncthreads();

    // outputs: scores[B,K] ++ bboxes[B,K,4] ++ keep[B,K]
    const int so = 0, bo = B_*K_, ko = B_*K_*5;
    for (int t = tid; t < K_; t += 1024) {
        unsigned long long key = g_topk[b][t];
        float val = __uint_as_float((unsigned)(key >> 32));
        bool kp = keepA[t] != 0;
        int g = b*K_ + t;
        if (so + g < out_size) out[so + g] = kp ? val : 0.f;
        if (bo + g*4 + 3 < out_size) {
            out[bo + g*4 + 0] = kp ? bx1[t] : 0.f;
            out[bo + g*4 + 1] = kp ? by1[t] : 0.f;
            out[bo + g*4 + 2] = kp ? bx2[t] : 0.f;
            out[bo + g*4 + 3] = kp ? by2[t] : 0.f;
        }
        if (ko + g < out_size) out[ko + g] = kp ? 1.f : 0.f;
    }
}

// ---------------- launch ----------------
extern "C" void kernel_launch(void* const* d_in, const int* in_sizes, int n_in,
                              void* d_out, int out_size) {
    (void)in_sizes; (void)n_in;
    const float* scores = (const float*)d_in[0];
    const float* deltas = (const float*)d_in[1];
    const float* sizes  = (const float*)d_in[2];
    const int* p_stride = (const int*)d_in[3];
    const int* p_offy   = (const int*)d_in[4];
    const int* p_offx   = (const int*)d_in[5];

    k_reset<<<17, 1024>>>();
    dim3 g1(H_ / RPB_, B_);
    k_cand<<<g1, 256>>>(scores);
    k_thresh<<<B_, 1024>>>();
    dim3 gc(NBUCK_ * 4, B_);
    k_compact<<<gc, 256>>>();
    dim3 gr(SURV_ / 256, B_);
    k_rank<<<gr, 256>>>(deltas, sizes, p_stride, p_offy, p_offx);
    k_nms<<<B_, 1024>>>((float*)d_out, out_size);
}

// round 10
// speedup vs baseline: 3.9471x; 1.1156x over previous
#include <cuda_runtime.h>
#include <cstdint>

#define B_ 8
#define H_ 1024
#define W_ 1024
#define HW_ (H_*W_)
#define K_ 2048
#define SURV_ 4096
#define NBIN_ 2048
#define NBUCK_ 128
#define CAPB_ 8192
#define NCELL_ 1024   /* 32x32 grid */
#define CELL_INV (1.0f/256.0f)
#define EMAX_ 512
#define RPB_ 8        /* rows per block in k_cand */
#define SBUF_ 2048    /* per-block candidate staging */

// ---------------- scratch (static device memory only) ----------------
__device__ unsigned long long g_bcand[B_][NBUCK_][CAPB_];  // bucketed candidates
__device__ unsigned g_bcnt[B_][NBUCK_];
__device__ unsigned g_base[B_][NBIN_];    // seg start = #keys in higher bins
__device__ unsigned g_segend[B_][NBIN_];  // seg end   = #keys in bins >= bin
__device__ unsigned long long g_surv[B_][SURV_];
__device__ int g_m[B_];
__device__ unsigned long long g_topk[B_][K_];
__device__ float4 g_box[B_][K_];

// ---------------- K0: zero bucket counters ----------------
__global__ void k_reset() {
    int g = threadIdx.x;
    if (g < B_ * NBUCK_) ((unsigned*)g_bcnt)[g] = 0u;
}

// ---------------- K1: local-max candidates (separable max9, bucketed emit) ----------------
// block = 8 image rows (256 threads x 4 px), grid = (H/8, B)
__global__ void __launch_bounds__(256) k_cand(const float* __restrict__ sc) {
    const int b = blockIdx.y, h0 = blockIdx.x * RPB_;
    const int tid = threadIdx.x;
    const int w0 = tid * 4;
    const int lane = tid & 31;
    const float NI = -__int_as_float(0x7f800000); // -inf

    __shared__ int scnt;
    __shared__ unsigned long long sbuf[SBUF_];
    __shared__ unsigned scntb[NBUCK_];
    __shared__ unsigned sbase[NBUCK_];
    __shared__ unsigned scur[NBUCK_];
    if (tid < NBUCK_) { scntb[tid] = 0u; scur[tid] = 0u; }
    if (tid == 0) scnt = 0;
    __syncthreads();

    float v[6], ha[4], hb[4], hc[4], c0[4], cn[4];

    #define LOADROW(hh) do {                                                \
        int _h = (hh);                                                      \
        if ((unsigned)_h >= (unsigned)H_) {                                 \
            v[0]=NI; v[1]=NI; v[2]=NI; v[3]=NI; v[4]=NI; v[5]=NI;           \
        } else {                                                            \
            const float* _r = sc + ((size_t)b * H_ + _h) * W_;              \
            float4 _m = *reinterpret_cast<const float4*>(_r + w0);          \
            float _lw = __shfl_up_sync(0xffffffffu, _m.w, 1);               \
            float _rx = __shfl_down_sync(0xffffffffu, _m.x, 1);             \
            v[1]=_m.x; v[2]=_m.y; v[3]=_m.z; v[4]=_m.w;                     \
            v[0] = lane        ? _lw : ((w0 > 0)      ? _r[w0-1] : NI);     \
            v[5] = (lane != 31)? _rx : ((w0 + 4 < W_) ? _r[w0+4] : NI);     \
        }                                                                   \
    } while (0)
    // horizontal 3-max of loaded row
    #define HMAX(dst) do {                                                  \
        dst[0] = fmaxf(fmaxf(v[0], v[1]), v[2]);                            \
        dst[1] = fmaxf(fmaxf(v[1], v[2]), v[3]);                            \
        dst[2] = fmaxf(fmaxf(v[2], v[3]), v[4]);                            \
        dst[3] = fmaxf(fmaxf(v[3], v[4]), v[5]);                            \
    } while (0)

    LOADROW(h0 - 1); HMAX(ha);
    LOADROW(h0);     HMAX(hb); c0[0]=v[1]; c0[1]=v[2]; c0[2]=v[3]; c0[3]=v[4];

    #pragma unroll
    for (int r = 0; r < RPB_; r++) {
        LOADROW(h0 + r + 1); HMAX(hc); cn[0]=v[1]; cn[1]=v[2]; cn[2]=v[3]; cn[3]=v[4];
        #pragma unroll
        for (int p = 0; p < 4; p++) {
            float s = c0[p];
            float pooled = fmaxf(fmaxf(ha[p], hb[p]), hc[p]);  // includes center
            if (s > 0.5f && s == pooled) {                      // reference mask exactly
                int pos = atomicAdd(&scnt, 1);
                if (pos < SBUF_) {
                    unsigned idx = (unsigned)((h0 + r) * W_ + w0 + p);
                    unsigned sb = __float_as_uint(s);
                    sbuf[pos] = ((unsigned long long)sb << 32) | (unsigned)(~idx);
                }
            }
        }
        #pragma unroll
        for (int q = 0; q < 4; q++) { ha[q]=hb[q]; hb[q]=hc[q]; c0[q]=cn[q]; }
    }
    __syncthreads();

    int c = scnt < SBUF_ ? scnt : SBUF_;
    // pass 0: per-bucket counts
    for (int i = tid; i < c; i += 256) {
        int bu = (int)((unsigned)(sbuf[i] >> 48) & (NBUCK_-1));
        atomicAdd(&scntb[bu], 1u);
    }
    __syncthreads();
    // reserve global ranges per non-empty bucket
    if (tid < NBUCK_) {
        unsigned cnt = scntb[tid];
        if (cnt) sbase[tid] = atomicAdd(&g_bcnt[b][tid], cnt);
    }
    __syncthreads();
    // pass 1: scatter
    for (int i = tid; i < c; i += 256) {
        unsigned long long key = sbuf[i];
        int bu = (int)((unsigned)(key >> 48) & (NBUCK_-1));
        unsigned pos = atomicAdd(&scur[bu], 1u) + sbase[bu];
        if (pos < CAPB_) g_bcand[b][bu][pos] = key;
    }
    #undef LOADROW
    #undef HMAX
}

// ---------------- K2: selection: coarse bucket -> fine hist -> threshold ->
//                    bases -> shared-cursor compaction (one CTA per batch) ----------------
__global__ void __launch_bounds__(1024) k_sel() {
    const int b = blockIdx.x, tid = threadIdx.x;
    __shared__ unsigned sfx[NBIN_];      // fine hist -> suffix sums -> cursors
    __shared__ unsigned sbcnt[NBUCK_];
    __shared__ int sB, sT;

    if (tid < NBUCK_) {
        unsigned cnt = g_bcnt[b][tid];
        sbcnt[tid] = cnt < CAPB_ ? cnt : CAPB_;
    }
    sfx[tid] = 0u; sfx[tid + 1024] = 0u;
    if (tid == 0) sT = 0;
    __syncthreads();

    // coarse: largest bucket B* with (#keys in buckets >= B*) >= K
    if (tid == 0) {
        unsigned acc = 0; int Bst = 0;
        for (int bu = NBUCK_-1; bu >= 0; bu--) {
            acc += sbcnt[bu];
            if (acc >= K_) { Bst = bu; break; }
        }
        sB = Bst;
    }
    __syncthreads();
    const int Bst = sB;

    // fine histogram of keys in surviving buckets (bins all >= Bst*16)
    for (int bu = Bst; bu < NBUCK_; bu++) {
        int cnt = (int)sbcnt[bu];
        for (int i = tid; i < cnt; i += 1024) {
            unsigned long long key = g_bcand[b][bu][i];
            atomicAdd(&sfx[(unsigned)(key >> 44) & (NBIN_-1)], 1u);
        }
    }
    __syncthreads();

    // inclusive suffix sums: sfx[i] = #counted keys with bin >= i
    for (int off = 1; off < NBIN_; off <<= 1) {
        unsigned v0 = sfx[tid]      + ((tid + off        < NBIN_) ? sfx[tid + off]        : 0u);
        unsigned v1 = sfx[tid+1024] + ((tid + 1024 + off < NBIN_) ? sfx[tid + 1024 + off] : 0u);
        __syncthreads();
        sfx[tid] = v0; sfx[tid + 1024] = v1;
        __syncthreads();
    }

    // threshold bin T: largest bin with suffix >= K (stays 0 if total < K)
    for (int i = tid; i < NBIN_; i += 1024) {
        unsigned s = sfx[i];
        unsigned nx = (i + 1 < NBIN_) ? sfx[i+1] : 0u;
        if (s >= K_ && nx < K_) sT = i;
    }
    __syncthreads();
    const int T = sT;
    unsigned M = sfx[T]; if (M > SURV_) M = SURV_;

    // per-bin base/segend to gmem; then convert sfx to scatter cursors
    unsigned base0, base1;
    {
        unsigned s0 = sfx[tid],      n0 = (tid + 1 < NBIN_)        ? sfx[tid+1]      : 0u;
        unsigned s1 = sfx[tid+1024], n1 = (tid + 1024 + 1 < NBIN_) ? sfx[tid+1024+1] : 0u;
        g_base[b][tid] = n0;        g_segend[b][tid] = s0;
        g_base[b][tid+1024] = n1;   g_segend[b][tid+1024] = s1;
        base0 = n0; base1 = n1;
    }
    __syncthreads();
    sfx[tid] = base0; sfx[tid + 1024] = base1;
    __syncthreads();

    // compaction with shared cursors
    for (int bu = Bst; bu < NBUCK_; bu++) {
        int cnt = (int)sbcnt[bu];
        for (int i = tid; i < cnt; i += 1024) {
            unsigned long long key = g_bcand[b][bu][i];
            int bin = (int)((unsigned)(key >> 44) & (NBIN_-1));
            if (bin >= T) {
                unsigned pos = atomicAdd(&sfx[bin], 1u);
                if (pos < SURV_) g_surv[b][pos] = key;
            }
        }
    }

    // zero topk + publish M
    for (int i = tid; i < K_; i += 1024) g_topk[b][i] = 0ull;
    if (tid == 0) g_m[b] = (int)M;
}

// ---------------- K3: exact rank within bin segment + scatter + box decode ----------------
__global__ void __launch_bounds__(256) k_rank(
    const float* __restrict__ deltas, const float* __restrict__ sizes,
    const int* __restrict__ p_stride, const int* __restrict__ p_offy,
    const int* __restrict__ p_offx)
{
    const int b = blockIdx.y;
    const int p = blockIdx.x * 256 + threadIdx.x;
    const int M = g_m[b];
    if (blockIdx.x * 256 >= M) return;
    if (p >= M) return;

    unsigned long long key = g_surv[b][p];
    int bin = (int)((unsigned)(key >> 44) & (NBIN_-1));
    int s0 = (int)g_base[b][bin];
    int e  = (int)g_segend[b][bin];
    if (e > SURV_) e = SURV_;

    int rank = s0;
    const unsigned long long* seg = g_surv[b];
    int m = s0;
    #pragma unroll 1
    for (; m + 4 <= e; m += 4) {
        rank += (seg[m]   > key);
        rank += (seg[m+1] > key);
        rank += (seg[m+2] > key);
        rank += (seg[m+3] > key);
    }
    for (; m < e; m++) rank += (seg[m] > key);

    if (rank < K_) {
        g_topk[b][rank] = key;
        // decode box (exact reference op order)
        const int stride = *p_stride, offy = *p_offy, offx = *p_offx;
        unsigned idx = ~(unsigned)key;
        int iw = (int)(idx & (W_-1)), ih = (int)(idx >> 10);
        float dx = deltas[((size_t)b*2 + 0)*HW_ + idx];
        float dy = deltas[((size_t)b*2 + 1)*HW_ + idx];
        float sx = sizes [((size_t)b*2 + 0)*HW_ + idx];
        float sy = sizes [((size_t)b*2 + 1)*HW_ + idx];
        float cx = (float)(iw*stride + offx) + dx;
        float cy = (float)(ih*stride + offy) + dy;
        float4 box;
        box.x = cx - sx*0.5f; box.y = cy - sy*0.5f;
        box.z = cx + sx*0.5f; box.w = cy + sy*0.5f;
        g_box[b][rank] = box;
    }
}

// ---------------- K4: sparse-edge greedy NMS + outputs ----------------
__global__ void __launch_bounds__(1024) k_nms(float* __restrict__ out, int out_size)
{
    const int b = blockIdx.x, tid = threadIdx.x;
    __shared__ float bx1[K_], by1[K_], bx2[K_], by2[K_];   // 32 KB
    __shared__ unsigned cellcnt[NCELL_];
    __shared__ unsigned short cstart[NCELL_ + 2];
    __shared__ unsigned short list[K_];
    __shared__ unsigned short cellof[K_];
    __shared__ unsigned char keepA[K_];
    __shared__ unsigned edges[EMAX_];
    __shared__ unsigned wsum[32];
    __shared__ int sE;

    if (tid == 0) sE = 0;
    cellcnt[tid] = 0;
    __syncthreads();

    // load boxes (coalesced) + bin into cells
    for (int t = tid; t < K_; t += 1024) {
        unsigned long long key = g_topk[b][t];
        float4 box = g_box[b][t];
        bool valid = key != 0ull;
        if (!valid) { box.x=0.f; box.y=0.f; box.z=0.f; box.w=0.f; }
        bx1[t]=box.x; by1[t]=box.y; bx2[t]=box.z; by2[t]=box.w;
        keepA[t] = valid ? 1 : 0;
        unsigned short cell = 0;
        if (valid) {
            int ccx = min(31, max(0, (int)floorf((box.x+box.z)*0.5f*CELL_INV)));
            int ccy = min(31, max(0, (int)floorf((box.y+box.w)*0.5f*CELL_INV)));
            cell = (unsigned short)(ccy*32 + ccx);
            atomicAdd(&cellcnt[cell], 1u);
        }
        cellof[t] = cell;
    }
    __syncthreads();

    // exclusive scan over 1024 cells -> cstart; cellcnt becomes scatter cursor
    {
        unsigned orig = cellcnt[tid];
        unsigned x = orig;
        int lane = tid & 31, wid = tid >> 5;
        for (int o = 1; o < 32; o <<= 1) {
            unsigned y = __shfl_up_sync(0xffffffffu, x, o);
            if (lane >= o) x += y;
        }
        if (lane == 31) wsum[wid] = x;
        __syncthreads();
        if (wid == 0) {
            unsigned s2 = wsum[lane];
            for (int o = 1; o < 32; o <<= 1) {
                unsigned y = __shfl_up_sync(0xffffffffu, s2, o);
                if (lane >= o) s2 += y;
            }
            wsum[lane] = s2;
        }
        __syncthreads();
        unsigned incl = x + (wid > 0 ? wsum[wid-1] : 0u);
        unsigned excl = incl - orig;
        cstart[tid] = (unsigned short)excl;
        if (tid == NCELL_-1) cstart[NCELL_] = (unsigned short)incl;
        __syncthreads();
        cellcnt[tid] = excl;
    }
    __syncthreads();

    // scatter boxes into cell-sorted list
    for (int t = tid; t < K_; t += 1024) {
        if (keepA[t]) {
            unsigned p = atomicAdd(&cellcnt[cellof[t]], 1u);
            list[p] = (unsigned short)t;
        }
    }
    __syncthreads();

    // sparse edge detection: pairs (i<j) with IoU > 0.5 via 3x3 cell neighborhood
    for (int t = tid; t < K_; t += 1024) {
        if (!keepA[t]) continue;
        float jx1=bx1[t], jy1=by1[t], jx2=bx2[t], jy2=by2[t];
        float aj = (jx2-jx1)*(jy2-jy1);
        int cc = cellof[t];
        int ccx = cc & 31, ccy = cc >> 5;
        int gy0 = max(ccy-1,0), gy1 = min(ccy+1,31);
        int gx0 = max(ccx-1,0), gx1 = min(ccx+1,31);
        for (int gy = gy0; gy <= gy1; gy++)
        for (int gx = gx0; gx <= gx1; gx++) {
            int c = gy*32 + gx;
            int pe = cstart[c+1];
            for (int p = cstart[c]; p < pe; p++) {
                int i = list[p];
                if (i >= t) continue;
                float xx1 = fmaxf(bx1[i], jx1);
                float yy1 = fmaxf(by1[i], jy1);
                float xx2 = fminf(bx2[i], jx2);
                float yy2 = fminf(by2[i], jy2);
                float iw2 = xx2 - xx1, ih2 = yy2 - yy1;
                if (iw2 <= 0.f || ih2 <= 0.f) continue;
                float inter = iw2 * ih2;
                float ai = (bx2[i]-bx1[i])*(by2[i]-by1[i]);
                float iou = inter / (ai + aj - inter + 1e-12f);
                if (iou > 0.5f) {
                    int e = atomicAdd(&sE, 1);
                    if (e < EMAX_) edges[e] = ((unsigned)t << 16) | (unsigned)i;
                }
            }
        }
    }
    __syncthreads();

    // exact greedy resolve: edges sorted ascending by suppressed index j
    if (tid == 0) {
        int E = sE; if (E > EMAX_) E = EMAX_;
        for (int a = 1; a < E; a++) {
            unsigned v = edges[a]; int q = a - 1;
            while (q >= 0 && edges[q] > v) { edges[q+1] = edges[q]; q--; }
            edges[q+1] = v;
        }
        for (int e = 0; e < E; e++) {
            int j = (int)(edges[e] >> 16), i = (int)(edges[e] & 0xffffu);
            if (keepA[i]) keepA[j] = 0;
        }
    }
    __syncthreads();

    // outputs: scores[B,K] ++ bboxes[B,K,4] ++ keep[B,K]
    const int so = 0, bo = B_*K_, ko = B_*K_*5;
    for (int t = tid; t < K_; t += 1024) {
        unsigned long long key = g_topk[b][t];
        float val = __uint_as_float((unsigned)(key >> 32));
        bool kp = keepA[t] != 0;
        int g = b*K_ + t;
        if (so + g < out_size) out[so + g] = kp ? val : 0.f;
        if (bo + g*4 + 3 < out_size) {
            float4 bx;
            bx.x = kp ? bx1[t] : 0.f;
            bx.y = kp ? by1[t] : 0.f;
            bx.z = kp ? bx2[t] : 0.f;
            bx.w = kp ? by2[t] : 0.f;
            *reinterpret_cast<float4*>(out + bo + g*4) = bx;
        }
        if (ko + g < out_size) out[ko + g] = kp ? 1.f : 0.f;
    }
}

// ---------------- launch ----------------
extern "C" void kernel_launch(void* const* d_in, const int* in_sizes, int n_in,
                              void* d_out, int out_size) {
    (void)in_sizes; (void)n_in;
    const float* scores = (const float*)d_in[0];
    const float* deltas = (const float*)d_in[1];
    const float* sizes  = (const float*)d_in[2];
    const int* p_stride = (const int*)d_in[3];
    const int* p_offy   = (const int*)d_in[4];
    const int* p_offx   = (const int*)d_in[5];

    k_reset<<<1, 1024>>>();
    dim3 g1(H_ / RPB_, B_);
    k_cand<<<g1, 256>>>(scores);
    k_sel<<<B_, 1024>>>();
    dim3 gr(SURV_ / 256, B_);
    k_rank<<<gr, 256>>>(deltas, sizes, p_stride, p_offy, p_offx);
    k_nms<<<B_, 1024>>>((float*)d_out, out_size);
}